// round 1
// baseline (speedup 1.0000x reference)
#include <cuda_runtime.h>

// FeatureExtractor_50165218017745
// Input : imgs_in [64, 3, 512, 512] float32 (values uniform in [0,1))
// Output: [64, 96, 4, 4] float32
//   ch  0..31 : full-image histogram (counts over all 3 channels) / (512*512), broadcast 4x4
//   ch 32..63 : per-quadrant histogram / (256*256), each quadrant fills its 2x2 block
//   ch 64..95 : zeros
//
// Strategy: atomic-free bit-sliced ballot histogram. Each warp is pinned to one
// (batch, quadrant); lane v accumulates the count of bin v in a register via
// 5 ballots (bin bit-planes) + XNOR/AND/POPC per 32 pixels. One global atomic
// per lane at warp exit.

#define BINS   32
#define BATCH  64
#define PARTS  8   // blocks per (batch, quadrant) tile

// (batch, quadrant, bin) integer counts; zeroed at the start of every launch.
__device__ unsigned g_counts[BATCH * 4 * BINS];

__global__ void zero_counts_kernel() {
    int i = blockIdx.x * blockDim.x + threadIdx.x;
    if (i < BATCH * 4 * BINS) g_counts[i] = 0u;
}

// bin = floor(x*32) for x in [0,1): FFMA.RZ with +2^23 puts floor(x*32) in the
// low mantissa bits (truncation toward zero drops the fraction). Clamp to 31
// to keep x == 1.0 safe. Inputs are guaranteed in [0,1).
__device__ __forceinline__ void accum_pixel(float x,
                                            unsigned m0, unsigned m1,
                                            unsigned m2, unsigned m3,
                                            unsigned m4, unsigned& cnt) {
    float y = __fmaf_rz(x, 32.0f, 8388608.0f);   // 2^23
    unsigned bi = __float_as_uint(y) & 63u;
    bi = umin(bi, 31u);
    unsigned p0 = __ballot_sync(0xFFFFFFFFu, (bi & 1u)  != 0u);
    unsigned p1 = __ballot_sync(0xFFFFFFFFu, (bi & 2u)  != 0u);
    unsigned p2 = __ballot_sync(0xFFFFFFFFu, (bi & 4u)  != 0u);
    unsigned p3 = __ballot_sync(0xFFFFFFFFu, (bi & 8u)  != 0u);
    unsigned p4 = __ballot_sync(0xFFFFFFFFu, (bi & 16u) != 0u);
    // bit j of e is set iff pixel j's bin == this lane's id
    unsigned e = ((p0 ^ m0) & (p1 ^ m1) & (p2 ^ m2)) & ((p3 ^ m3) & (p4 ^ m4));
    cnt += (unsigned)__popc(e);
}

__global__ __launch_bounds__(256)
void hist_kernel(const float* __restrict__ in) {
    // bid = ((b*4 + q) * PARTS + part)
    int bid  = blockIdx.x;
    int part = bid & (PARTS - 1);
    int q    = (bid >> 3) & 3;
    int b    = bid >> 5;
    int qy   = q >> 1;
    int qx   = q & 1;

    int warp = threadIdx.x >> 5;
    int lane = threadIdx.x & 31;

    // lane owns bin == lane; m_i = (bit i of lane) ? 0 : ~0  (for XNOR)
    unsigned m0 = (lane & 1)  ? 0u : 0xFFFFFFFFu;
    unsigned m1 = (lane & 2)  ? 0u : 0xFFFFFFFFu;
    unsigned m2 = (lane & 4)  ? 0u : 0xFFFFFFFFu;
    unsigned m3 = (lane & 8)  ? 0u : 0xFFFFFFFFu;
    unsigned m4 = (lane & 16) ? 0u : 0xFFFFFFFFu;

    unsigned cnt = 0;

    // 768 quadrant-rows per tile (3 channels x 256 rows), 64 warp-stripes.
    int wi = part * 8 + warp;   // 0..63
    for (int ridx = wi; ridx < 768; ridx += 64) {
        int c = ridx >> 8;      // channel 0..2
        int r = ridx & 255;     // row within quadrant
        const float4* p = (const float4*)(in
            + (((((b * 3 + c) << 9) + (qy << 8) + r) << 9) + (qx << 8)));
        float4 v0 = p[lane];        // floats [lane*4 .. lane*4+3]
        float4 v1 = p[lane + 32];   // floats [128+lane*4 ..]
        accum_pixel(v0.x, m0, m1, m2, m3, m4, cnt);
        accum_pixel(v0.y, m0, m1, m2, m3, m4, cnt);
        accum_pixel(v0.z, m0, m1, m2, m3, m4, cnt);
        accum_pixel(v0.w, m0, m1, m2, m3, m4, cnt);
        accum_pixel(v1.x, m0, m1, m2, m3, m4, cnt);
        accum_pixel(v1.y, m0, m1, m2, m3, m4, cnt);
        accum_pixel(v1.z, m0, m1, m2, m3, m4, cnt);
        accum_pixel(v1.w, m0, m1, m2, m3, m4, cnt);
    }

    atomicAdd(&g_counts[((b << 2) + q) * BINS + lane], cnt);
}

__global__ void finalize_kernel(float* __restrict__ out) {
    int o = blockIdx.x * blockDim.x + threadIdx.x;
    if (o >= BATCH * 96 * 16) return;
    int b    = o / 1536;
    int rem  = o - b * 1536;
    int ch   = rem >> 4;
    int cell = rem & 15;

    const unsigned* cb = g_counts + b * (4 * BINS);
    float val = 0.0f;
    if (ch < 32) {
        unsigned s = cb[ch] + cb[BINS + ch] + cb[2 * BINS + ch] + cb[3 * BINS + ch];
        val = (float)s * (1.0f / 262144.0f);          // / (512*512)
    } else if (ch < 64) {
        int bin = ch - 32;
        int y = cell >> 2, x = cell & 3;
        int q = ((y >> 1) << 1) | (x >> 1);
        val = (float)cb[q * BINS + bin] * (1.0f / 65536.0f);  // / (256*256)
    }
    out[o] = val;
}

extern "C" void kernel_launch(void* const* d_in, const int* in_sizes, int n_in,
                              void* d_out, int out_size) {
    (void)in_sizes; (void)n_in; (void)out_size;
    const float* in = (const float*)d_in[0];
    float* out = (float*)d_out;

    zero_counts_kernel<<<32, 256>>>();
    hist_kernel<<<BATCH * 4 * PARTS, 256>>>(in);     // 2048 blocks
    finalize_kernel<<<384, 256>>>(out);              // 384*256 = 98304 = 64*96*16
}

// round 2
// speedup vs baseline: 1.8480x; 1.8480x over previous
#include <cuda_runtime.h>

// FeatureExtractor_50165218017745
// Input : imgs_in [64, 3, 512, 512] float32 in [0,1)
// Output: [64, 96, 4, 4] float32
//   ch  0..31 : full-image hist / (512*512), broadcast over 4x4
//   ch 32..63 : per-quadrant hist / (256*256), each quadrant -> its 2x2 block
//   ch 64..95 : zeros
//
// R2 strategy: per-thread privatized shared-memory histograms.
// hist[bin*256 + tid]: bank = tid%32 -> conflict-free updates for ANY bin
// pattern, no atomics, no votes. Block partials -> plain global stores
// (no zeroing kernel), summed by a tiny finalize kernel.

#define BINS   32
#define BATCH  64
#define PARTS  4              // blocks per (batch, quadrant): 64*4*4 = 1024 blocks
#define NBLK   (BATCH * 4 * PARTS)

// per-block partial counts [block][bin]; fully overwritten every run
__device__ unsigned g_part[NBLK * BINS];

// bin = floor(32x) for x in [0,1): FFMA.RZ + 2^23 leaves floor(32x) in the
// low mantissa bits (exact for 0 <= 32x < 2^23).
__device__ __forceinline__ unsigned bin_of(float x) {
    return __float_as_uint(__fmaf_rz(x, 32.0f, 8388608.0f)) & 31u;
}

__device__ __forceinline__ void bump8(const float4& a, const float4& b,
                                      unsigned* __restrict__ h) {
    h[bin_of(a.x) << 8] += 1u;
    h[bin_of(a.y) << 8] += 1u;
    h[bin_of(a.z) << 8] += 1u;
    h[bin_of(a.w) << 8] += 1u;
    h[bin_of(b.x) << 8] += 1u;
    h[bin_of(b.y) << 8] += 1u;
    h[bin_of(b.z) << 8] += 1u;
    h[bin_of(b.w) << 8] += 1u;
}

__device__ __forceinline__ const float4* row_ptr(const float* __restrict__ in,
                                                 int b, int qy, int qx, int ridx) {
    int c = ridx >> 8;        // channel 0..2
    int r = ridx & 255;       // row within quadrant
    return (const float4*)(in + (((((b * 3 + c) << 9) + (qy << 8) + r) << 9) + (qx << 8)));
}

__global__ __launch_bounds__(256)
void hist_kernel(const float* __restrict__ in) {
    __shared__ unsigned hist[BINS * 256];   // 32 KB: [bin][tid]

    int bid  = blockIdx.x;                  // ((b*4 + q) * PARTS + part)
    int part = bid & (PARTS - 1);
    int q    = (bid >> 2) & 3;
    int b    = bid >> 4;
    int qy   = q >> 1;
    int qx   = q & 1;

    int tid  = threadIdx.x;
    int warp = tid >> 5;
    int lane = tid & 31;

    // zero private histograms (8192 words / 256 threads = 8 uint4 each)
    {
        uint4* z = (uint4*)hist;
        #pragma unroll
        for (int i = 0; i < 8; i++)
            z[tid + 256 * i] = make_uint4(0u, 0u, 0u, 0u);
    }
    __syncthreads();

    unsigned* h = hist + tid;

    // 768 quadrant-rows (3 ch x 256 rows); 32 warp-stripes -> 24 rows/warp.
    int ridx = part * 8 + warp;             // 0..31
    const float4* p = row_ptr(in, b, qy, qx, ridx);
    float4 v0 = p[lane];
    float4 v1 = p[lane + 32];

    #pragma unroll 4
    for (int it = 0; it < 23; ++it) {
        ridx += 32;
        const float4* np = row_ptr(in, b, qy, qx, ridx);
        float4 n0 = np[lane];
        float4 n1 = np[lane + 32];
        bump8(v0, v1, h);
        v0 = n0; v1 = n1;
    }
    bump8(v0, v1, h);

    __syncthreads();

    // Block reduction: 8192 counters -> 32 bin sums.
    // thread t: bin = t&31, chunk = t>>5; rotated index -> conflict-free.
    unsigned s = 0;
    int base = (tid & 31) * 256 + (tid >> 5) * 32;
    #pragma unroll
    for (int i = 0; i < 32; i++)
        s += hist[base + ((i + tid) & 31)];
    __syncthreads();                        // all reads done before reuse
    hist[tid] = s;                          // reuse hist[0..255] as scratch
    __syncthreads();
    if (tid < 32) {
        unsigned tot = 0;
        #pragma unroll
        for (int c = 0; c < 8; c++)
            tot += hist[tid + 32 * c];
        g_part[bid * BINS + tid] = tot;     // plain store, no atomics
    }
}

__global__ __launch_bounds__(256)
void finalize_kernel(float* __restrict__ out) {
    __shared__ float s1[4 * BINS];          // per-quadrant hist / 65536
    __shared__ float s0[BINS];              // full-image hist / 262144

    int b = blockIdx.x;
    int t = threadIdx.x;

    if (t < 128) {
        int qq  = t >> 5;
        int bin = t & 31;
        unsigned s = 0;
        #pragma unroll
        for (int p = 0; p < PARTS; p++)
            s += g_part[(((b * 4 + qq) * PARTS) + p) * BINS + bin];
        s1[qq * BINS + bin] = (float)s * (1.0f / 65536.0f);
    }
    __syncthreads();
    if (t < 32)
        s0[t] = (s1[t] + s1[32 + t] + s1[64 + t] + s1[96 + t]) * 0.25f;
    __syncthreads();

    #pragma unroll
    for (int k = 0; k < 6; k++) {
        int idx  = t + 256 * k;             // 0..1535
        int ch   = idx >> 4;
        int cell = idx & 15;                // y*4 + x
        float v = 0.0f;
        if (ch < 32) {
            v = s0[ch];
        } else if (ch < 64) {
            int qq = ((cell >> 3) << 1) | ((cell >> 1) & 1);  // (y>>1)*2 + (x>>1)
            v = s1[qq * BINS + (ch - 32)];
        }
        out[b * 1536 + idx] = v;
    }
}

extern "C" void kernel_launch(void* const* d_in, const int* in_sizes, int n_in,
                              void* d_out, int out_size) {
    (void)in_sizes; (void)n_in; (void)out_size;
    const float* in = (const float*)d_in[0];
    float* out = (float*)d_out;

    hist_kernel<<<NBLK, 256>>>(in);         // 1024 blocks, one wave @ 7 CTA/SM
    finalize_kernel<<<BATCH, 256>>>(out);
}

// round 3
// speedup vs baseline: 1.9227x; 1.0404x over previous
#include <cuda_runtime.h>

// FeatureExtractor_50165218017745  (R3: fused single-kernel)
// Input : imgs_in [64, 3, 512, 512] float32 in [0,1)
// Output: [64, 96, 4, 4] float32
//
// Per-thread privatized smem histograms (conflict-free: bank = tid%32 for any
// bin), depth-2 LDG.128 pipeline, and a fused threadfence-reduction epilogue:
// the last block of each batch finalizes that batch's outputs in-overlap and
// resets the global scratch for the next graph replay.

#define BINS   32
#define BATCH  64
#define PARTS  4
#define NBLK   (BATCH * 4 * PARTS)   // 1024 blocks

__device__ unsigned g_counts[BATCH * 4 * BINS];  // zero-init; reset each run
__device__ unsigned g_done[BATCH];               // zero-init; reset each run

// bin = floor(32x) for x in [0,1): FFMA.RZ + 2^23 leaves floor(32x) in the
// low mantissa bits (exact for 0 <= 32x < 2^23).
__device__ __forceinline__ unsigned bin_of(float x) {
    return __float_as_uint(__fmaf_rz(x, 32.0f, 8388608.0f)) & 31u;
}

__device__ __forceinline__ void bump8(const float4& a, const float4& b,
                                      unsigned* __restrict__ h) {
    h[bin_of(a.x) << 8] += 1u;
    h[bin_of(a.y) << 8] += 1u;
    h[bin_of(a.z) << 8] += 1u;
    h[bin_of(a.w) << 8] += 1u;
    h[bin_of(b.x) << 8] += 1u;
    h[bin_of(b.y) << 8] += 1u;
    h[bin_of(b.z) << 8] += 1u;
    h[bin_of(b.w) << 8] += 1u;
}

__device__ __forceinline__ const float4* row_ptr(const float* __restrict__ in,
                                                 int b, int qy, int qx, int ridx) {
    int c = ridx >> 8;        // channel 0..2
    int r = ridx & 255;       // row within quadrant
    return (const float4*)(in + (((((b * 3 + c) << 9) + (qy << 8) + r) << 9) + (qx << 8)));
}

__global__ __launch_bounds__(256)
void fused_kernel(const float* __restrict__ in, float* __restrict__ out) {
    __shared__ unsigned hist[BINS * 256];   // exactly 32 KB: [bin][tid]

    int bid  = blockIdx.x;                  // ((b*4 + q) * PARTS + part)
    int part = bid & (PARTS - 1);
    int q    = (bid >> 2) & 3;
    int b    = bid >> 4;
    int qy   = q >> 1;
    int qx   = q & 1;

    int tid  = threadIdx.x;
    int warp = tid >> 5;
    int lane = tid & 31;

    // zero private histograms
    {
        uint4* z = (uint4*)hist;
        #pragma unroll
        for (int i = 0; i < 8; i++)
            z[tid + 256 * i] = make_uint4(0u, 0u, 0u, 0u);
    }
    __syncthreads();

    unsigned* h = hist + tid;

    // 768 quadrant-rows (3 ch x 256); 32 warp-stripes -> 24 rows/warp.
    // Depth-2 software pipeline: 2 rows (4 LDG.128) in flight.
    int ridx = part * 8 + warp;             // 0..31
    const float4* p0 = row_ptr(in, b, qy, qx, ridx);
    const float4* p1 = row_ptr(in, b, qy, qx, ridx + 32);
    float4 a0 = p0[lane], a1 = p0[lane + 32];
    float4 b0 = p1[lane], b1 = p1[lane + 32];

    #pragma unroll 2
    for (int k = 2; k < 24; ++k) {
        const float4* p2 = row_ptr(in, b, qy, qx, ridx + 32 * k);
        float4 c0 = p2[lane], c1 = p2[lane + 32];
        bump8(a0, a1, h);
        a0 = b0; a1 = b1;
        b0 = c0; b1 = c1;
    }
    bump8(a0, a1, h);
    bump8(b0, b1, h);
    __syncthreads();

    // Block reduction: 8192 counters -> 32 bin sums (rotated, conflict-free).
    unsigned s = 0;
    int base = (tid & 31) * 256 + (tid >> 5) * 32;
    #pragma unroll
    for (int i = 0; i < 32; i++)
        s += hist[base + ((i + tid) & 31)];
    __syncthreads();
    hist[tid] = s;                          // reuse hist[0..255] as scratch
    __syncthreads();
    if (tid < 32) {
        unsigned tot = 0;
        #pragma unroll
        for (int c = 0; c < 8; c++)
            tot += hist[tid + 32 * c];
        atomicAdd(&g_counts[((b << 2) + q) * BINS + tid], tot);
    }

    // Release our counts, then bump the per-batch arrival counter.
    __threadfence();                        // each writer orders its atomic
    __syncthreads();
    if (tid == 0)
        hist[256] = atomicAdd(&g_done[b], 1u);
    __syncthreads();
    unsigned rank = hist[256];
    if (rank != 4 * PARTS - 1) return;      // not the last block of batch b

    // ---- last block of batch b: finalize (overlapped with other batches) ----
    __threadfence();                        // acquire
    __syncthreads();

    float* s1  = (float*)hist;              // [128]: per-quadrant hist / 65536
    float* s0v = (float*)(hist + 128);      // [32] : full-image hist / 262144

    if (tid < 128) {
        unsigned c = __ldcg(&g_counts[(b << 7) + tid]);  // L2-coherent read
        s1[tid] = (float)c * (1.0f / 65536.0f);
        g_counts[(b << 7) + tid] = 0u;      // reset for next replay
    }
    __syncthreads();
    if (tid < 32)
        s0v[tid] = (s1[tid] + s1[32 + tid] + s1[64 + tid] + s1[96 + tid]) * 0.25f;
    if (tid == 0)
        g_done[b] = 0u;                     // reset for next replay
    __syncthreads();

    #pragma unroll
    for (int k = 0; k < 6; k++) {
        int idx  = tid + 256 * k;           // 0..1535
        int ch   = idx >> 4;
        int cell = idx & 15;                // y*4 + x
        float v = 0.0f;
        if (ch < 32) {
            v = s0v[ch];
        } else if (ch < 64) {
            int qq = ((cell >> 3) << 1) | ((cell >> 1) & 1);  // (y>>1)*2+(x>>1)
            v = s1[qq * BINS + (ch - 32)];
        }
        out[b * 1536 + idx] = v;
    }
}

extern "C" void kernel_launch(void* const* d_in, const int* in_sizes, int n_in,
                              void* d_out, int out_size) {
    (void)in_sizes; (void)n_in; (void)out_size;
    fused_kernel<<<NBLK, 256>>>((const float*)d_in[0], (float*)d_out);
}

// round 4
// speedup vs baseline: 2.2258x; 1.1576x over previous
#include <cuda_runtime.h>

// FeatureExtractor_50165218017745  (R4: single-wave, u16 counters)
// Input : imgs_in [64, 3, 512, 512] float32 in [0,1)
// Output: [64, 96, 4, 4] float32
//
// Per-thread privatized smem histograms in u16 (16 KB/CTA; per-thread max
// count 192 << 65535), depth-1 LDG.128 prefetch, __launch_bounds__(256,7)
// -> 7 CTAs/SM, 1036 resident >= 1024 blocks = ONE wave.
// Fused threadfence-reduction epilogue finalizes each batch in-overlap and
// resets global scratch for graph replay.

#define BINS   32
#define BATCH  64
#define PARTS  4
#define NBLK   (BATCH * 4 * PARTS)   // 1024 blocks

__device__ unsigned g_counts[BATCH * 4 * BINS];  // zero-init; reset each run
__device__ unsigned g_done[BATCH];               // zero-init; reset each run

// bin = floor(32x) for x in [0,1): FFMA.RZ + 2^23 leaves floor(32x) in the
// low mantissa bits (exact for 0 <= 32x < 2^23).
__device__ __forceinline__ unsigned bin_of(float x) {
    return __float_as_uint(__fmaf_rz(x, 32.0f, 8388608.0f)) & 31u;
}

__device__ __forceinline__ void bump8(const float4& a, const float4& b,
                                      unsigned short* __restrict__ h) {
    h[bin_of(a.x) << 8] += 1u;
    h[bin_of(a.y) << 8] += 1u;
    h[bin_of(a.z) << 8] += 1u;
    h[bin_of(a.w) << 8] += 1u;
    h[bin_of(b.x) << 8] += 1u;
    h[bin_of(b.y) << 8] += 1u;
    h[bin_of(b.z) << 8] += 1u;
    h[bin_of(b.w) << 8] += 1u;
}

__device__ __forceinline__ const float4* row_ptr(const float* __restrict__ in,
                                                 int b, int qy, int qx, int ridx) {
    int c = ridx >> 8;        // channel 0..2
    int r = ridx & 255;       // row within quadrant
    return (const float4*)(in + (((((b * 3 + c) << 9) + (qy << 8) + r) << 9) + (qx << 8)));
}

__global__ __launch_bounds__(256, 7)
void fused_kernel(const float* __restrict__ in, float* __restrict__ out) {
    __shared__ unsigned short hist[BINS * 256];   // 16 KB: [bin][tid], u16
    __shared__ unsigned scratch[256 + 1];         // reduction + rank

    int bid  = blockIdx.x;                  // ((b*4 + q) * PARTS + part)
    int part = bid & (PARTS - 1);
    int q    = (bid >> 2) & 3;
    int b    = bid >> 4;
    int qy   = q >> 1;
    int qx   = q & 1;

    int tid  = threadIdx.x;
    int warp = tid >> 5;
    int lane = tid & 31;

    // zero private histograms (4096 words / 256 threads = 4 uint4 each)
    {
        uint4* z = (uint4*)hist;
        #pragma unroll
        for (int i = 0; i < 4; i++)
            z[tid + 256 * i] = make_uint4(0u, 0u, 0u, 0u);
    }
    __syncthreads();

    unsigned short* h = hist + tid;

    // 768 quadrant-rows (3 ch x 256); 32 warp-stripes -> 24 rows/warp.
    // Depth-1 prefetch: next row's 2 LDG.128 in flight while binning current.
    int ridx = part * 8 + warp;             // 0..31
    const float4* p = row_ptr(in, b, qy, qx, ridx);
    float4 v0 = p[lane];
    float4 v1 = p[lane + 32];

    #pragma unroll 4
    for (int it = 0; it < 23; ++it) {
        ridx += 32;
        const float4* np = row_ptr(in, b, qy, qx, ridx);
        float4 n0 = np[lane];
        float4 n1 = np[lane + 32];
        bump8(v0, v1, h);
        v0 = n0; v1 = n1;
    }
    bump8(v0, v1, h);
    __syncthreads();

    // Block reduction: 8192 u16 counters -> 32 bin sums (rotated).
    unsigned s = 0;
    int base = (tid & 31) * 256 + (tid >> 5) * 32;
    #pragma unroll
    for (int i = 0; i < 32; i++)
        s += hist[base + ((i + tid) & 31)];
    scratch[tid] = s;
    __syncthreads();
    if (tid < 32) {
        unsigned tot = 0;
        #pragma unroll
        for (int c = 0; c < 8; c++)
            tot += scratch[tid + 32 * c];
        atomicAdd(&g_counts[((b << 2) + q) * BINS + tid], tot);
    }

    // Release counts, then bump per-batch arrival counter.
    __threadfence();
    __syncthreads();
    if (tid == 0)
        scratch[256] = atomicAdd(&g_done[b], 1u);
    __syncthreads();
    unsigned rank = scratch[256];
    if (rank != 4 * PARTS - 1) return;      // not the last block of batch b

    // ---- last block of batch b: finalize (overlapped with other batches) ----
    __threadfence();                        // acquire
    __syncthreads();

    float* s1  = (float*)hist;              // [128]: per-quadrant hist / 65536
    float* s0v = ((float*)hist) + 128;      // [32] : full-image hist / 262144

    if (tid < 128) {
        unsigned c = __ldcg(&g_counts[(b << 7) + tid]);
        s1[tid] = (float)c * (1.0f / 65536.0f);
        g_counts[(b << 7) + tid] = 0u;      // reset for next replay
    }
    __syncthreads();
    if (tid < 32)
        s0v[tid] = (s1[tid] + s1[32 + tid] + s1[64 + tid] + s1[96 + tid]) * 0.25f;
    if (tid == 0)
        g_done[b] = 0u;                     // reset for next replay
    __syncthreads();

    #pragma unroll
    for (int k = 0; k < 6; k++) {
        int idx  = tid + 256 * k;           // 0..1535
        int ch   = idx >> 4;
        int cell = idx & 15;                // y*4 + x
        float v = 0.0f;
        if (ch < 32) {
            v = s0v[ch];
        } else if (ch < 64) {
            int qq = ((cell >> 3) << 1) | ((cell >> 1) & 1);  // (y>>1)*2+(x>>1)
            v = s1[qq * BINS + (ch - 32)];
        }
        out[b * 1536 + idx] = v;
    }
}

extern "C" void kernel_launch(void* const* d_in, const int* in_sizes, int n_in,
                              void* d_out, int out_size) {
    (void)in_sizes; (void)n_in; (void)out_size;
    fused_kernel<<<NBLK, 256>>>((const float*)d_in[0], (float*)d_out);
}

// round 5
// speedup vs baseline: 2.3191x; 1.0419x over previous
#include <cuda_runtime.h>

// FeatureExtractor_50165218017745  (R5: conflict-free parity-packed u16)
// Input : imgs_in [64, 3, 512, 512] float32 in [0,1)
// Output: [64, 96, 4, 4] float32
//
// Per-thread privatized smem histograms, u16, parity-packed so that
// bank == lane for every access (word = bin*128 + (warp>>1)*32 + lane,
// halfword = warp&1): zero bank conflicts for arbitrary bin patterns.
// 16 KB smem + <=36 regs -> 7 CTAs/SM -> 1024-block grid in ONE wave.
// Fused threadfence-reduction epilogue finalizes per-batch outputs in
// overlap and resets global scratch for graph replay.

#define BINS   32
#define BATCH  64
#define PARTS  4
#define NBLK   (BATCH * 4 * PARTS)   // 1024 blocks

__device__ unsigned g_counts[BATCH * 4 * BINS];  // zero-init; reset each run
__device__ unsigned g_done[BATCH];               // zero-init; reset each run

// bin = floor(32x) for x in [0,1): FFMA.RZ + 2^23 leaves floor(32x) in the
// low mantissa bits (exact for 0 <= 32x < 2^23).
__device__ __forceinline__ unsigned bin_of(float x) {
    return __float_as_uint(__fmaf_rz(x, 32.0f, 8388608.0f)) & 31u;
}

__device__ __forceinline__ void bump8(const float4& a, const float4& b,
                                      unsigned short* __restrict__ h) {
    h[bin_of(a.x) << 8] += 1u;
    h[bin_of(a.y) << 8] += 1u;
    h[bin_of(a.z) << 8] += 1u;
    h[bin_of(a.w) << 8] += 1u;
    h[bin_of(b.x) << 8] += 1u;
    h[bin_of(b.y) << 8] += 1u;
    h[bin_of(b.z) << 8] += 1u;
    h[bin_of(b.w) << 8] += 1u;
}

__device__ __forceinline__ const float4* row_ptr(const float* __restrict__ in,
                                                 int b, int qy, int qx, int ridx) {
    int c = ridx >> 8;        // channel 0..2
    int r = ridx & 255;       // row within quadrant
    return (const float4*)(in + (((((b * 3 + c) << 9) + (qy << 8) + r) << 9) + (qx << 8)));
}

__global__ __launch_bounds__(256, 7)
void fused_kernel(const float* __restrict__ in, float* __restrict__ out) {
    __shared__ unsigned short hist[BINS * 256];   // 16 KB
    __shared__ unsigned scratch[256 + 1];         // reduction + rank

    int bid  = blockIdx.x;                  // ((b*4 + q) * PARTS + part)
    int part = bid & (PARTS - 1);
    int q    = (bid >> 2) & 3;
    int b    = bid >> 4;
    int qy   = q >> 1;
    int qx   = q & 1;

    int tid  = threadIdx.x;
    int warp = tid >> 5;
    int lane = tid & 31;

    // zero private histograms (4096 words / 256 threads = 4 uint4 each)
    {
        uint4* z = (uint4*)hist;
        #pragma unroll
        for (int i = 0; i < 4; i++)
            z[tid + 256 * i] = make_uint4(0u, 0u, 0u, 0u);
    }
    __syncthreads();

    // Parity-packed slot: u16 index = bin*256 + (warp>>1)*64 + lane*2 + (warp&1)
    // -> byte = bin*512 + (warp>>1)*128 + lane*4 + (warp&1)*2 -> bank = lane.
    unsigned short* h = hist + ((warp >> 1) << 6) + (lane << 1) + (warp & 1);

    // 768 quadrant-rows (3 ch x 256); 32 warp-stripes -> 24 rows/warp.
    // Depth-1 prefetch: next row's 2 LDG.128 in flight while binning current.
    int ridx = part * 8 + warp;             // 0..31
    const float4* p = row_ptr(in, b, qy, qx, ridx);
    float4 v0 = p[lane];
    float4 v1 = p[lane + 32];

    #pragma unroll 4
    for (int it = 0; it < 23; ++it) {
        ridx += 32;
        const float4* np = row_ptr(in, b, qy, qx, ridx);
        float4 n0 = np[lane];
        float4 n1 = np[lane + 32];
        bump8(v0, v1, h);
        v0 = n0; v1 = n1;
    }
    bump8(v0, v1, h);
    __syncthreads();

    // Block reduction: for bin b, u16 range [b*256, b*256+256) holds all 256
    // per-thread counters (permuted) -> layout-agnostic sum, rotated reads.
    unsigned s = 0;
    int base = (tid & 31) * 256 + (tid >> 5) * 32;
    #pragma unroll
    for (int i = 0; i < 32; i++)
        s += hist[base + ((i + tid) & 31)];
    scratch[tid] = s;
    __syncthreads();
    if (tid < 32) {
        unsigned tot = 0;
        #pragma unroll
        for (int c = 0; c < 8; c++)
            tot += scratch[tid + 32 * c];
        atomicAdd(&g_counts[((b << 2) + q) * BINS + tid], tot);
    }

    // Release counts, then bump per-batch arrival counter.
    __threadfence();
    __syncthreads();
    if (tid == 0)
        scratch[256] = atomicAdd(&g_done[b], 1u);
    __syncthreads();
    unsigned rank = scratch[256];
    if (rank != 4 * PARTS - 1) return;      // not the last block of batch b

    // ---- last block of batch b: finalize (overlapped with other batches) ----
    __threadfence();                        // acquire
    __syncthreads();

    float* s1  = (float*)hist;              // [128]: per-quadrant hist / 65536
    float* s0v = ((float*)hist) + 128;      // [32] : full-image hist / 262144

    if (tid < 128) {
        unsigned c = __ldcg(&g_counts[(b << 7) + tid]);
        s1[tid] = (float)c * (1.0f / 65536.0f);
        g_counts[(b << 7) + tid] = 0u;      // reset for next replay
    }
    __syncthreads();
    if (tid < 32)
        s0v[tid] = (s1[tid] + s1[32 + tid] + s1[64 + tid] + s1[96 + tid]) * 0.25f;
    if (tid == 0)
        g_done[b] = 0u;                     // reset for next replay
    __syncthreads();

    #pragma unroll
    for (int k = 0; k < 6; k++) {
        int idx  = tid + 256 * k;           // 0..1535
        int ch   = idx >> 4;
        int cell = idx & 15;                // y*4 + x
        float v = 0.0f;
        if (ch < 32) {
            v = s0v[ch];
        } else if (ch < 64) {
            int qq = ((cell >> 3) << 1) | ((cell >> 1) & 1);  // (y>>1)*2+(x>>1)
            v = s1[qq * BINS + (ch - 32)];
        }
        out[b * 1536 + idx] = v;
    }
}

extern "C" void kernel_launch(void* const* d_in, const int* in_sizes, int n_in,
                              void* d_out, int out_size) {
    (void)in_sizes; (void)n_in; (void)out_size;
    fused_kernel<<<NBLK, 256>>>((const float*)d_in[0], (float*)d_out);
}